// round 4
// baseline (speedup 1.0000x reference)
#include <cuda_runtime.h>
#include <cuda_bf16.h>

// CWTConv2D: quantized 3x3 valid conv.
// out[b,i,j,f] = relu( sum_{u,v} round(x[b,i+u,j+v]) * clip(round(kw[f,2-u,2-v]),-1,1)
//                      + round(bias[f]) )
// Shapes: x (32,512,512) f32, kw (32,3,3) f32, bias (32,) f32
// out (32,510,510,32) f32, NHWC (f fastest).

#define BATCH   32
#define HW      512
#define OHW     510
#define NF      32
#define TR      8      // output rows per block (one per warp)
#define TC      128    // output cols per block
#define SM_COLS (TC + 2)    // 130 input cols needed
#define SM_ROWS (TR + 2)    // 10 input rows needed
#define SM_STRIDE 132       // padded row stride in smem

__global__ __launch_bounds__(256)
void cwtconv2d_kernel(const float* __restrict__ x,
                      const float* __restrict__ kw,
                      const float* __restrict__ bias,
                      float* __restrict__ out)
{
    __shared__ float sx[SM_ROWS * SM_STRIDE];

    const int b   = blockIdx.z;
    const int gr0 = blockIdx.y * TR;   // first output row of this block
    const int gc0 = blockIdx.x * TC;   // first output col of this block
    const int tid  = threadIdx.x;
    const int lane = tid & 31;         // = filter index f
    const int wrp  = tid >> 5;         // = row within tile

    // ---- per-lane weights: quantize + spatial flip (so inner loop is a
    //      straight dot product with the x patch in raster order) ----
    float wf[9];
    #pragma unroll
    for (int k = 0; k < 9; ++k) {
        float v = rintf(__ldg(&kw[lane * 9 + (8 - k)]));  // k_q[f, 2-u, 2-v]
        wf[k] = fminf(fmaxf(v, -1.0f), 1.0f);
    }
    const float bia = rintf(__ldg(&bias[lane]));

    // ---- cooperative smem fill: pre-rounded input tile ----
    const float* xb = x + (size_t)b * HW * HW;
    for (int idx = tid; idx < SM_ROWS * SM_COLS; idx += 256) {
        int r = idx / SM_COLS;
        int c = idx - r * SM_COLS;
        int gr = gr0 + r;
        int gc = gc0 + c;
        float v = 0.0f;
        if (gr < HW && gc < HW) v = rintf(xb[gr * HW + gc]);
        sx[r * SM_STRIDE + c] = v;
    }
    __syncthreads();

    // ---- each warp computes one output row; lane = filter channel ----
    const int i = gr0 + wrp;
    if (i >= OHW) return;

    int jmax = OHW - gc0;
    if (jmax > TC) jmax = TC;

    const float* r0 = &sx[(wrp + 0) * SM_STRIDE];
    const float* r1 = &sx[(wrp + 1) * SM_STRIDE];
    const float* r2 = &sx[(wrp + 2) * SM_STRIDE];

    // sliding 3x3 window registers (columns j, j+1 held, j+2 loaded per step)
    float x00 = r0[0], x01 = r0[1];
    float x10 = r1[0], x11 = r1[1];
    float x20 = r2[0], x21 = r2[1];

    // warp writes 32 consecutive floats (128 B) per pixel -> perfectly coalesced
    float* optr = out + ((((size_t)b * OHW + i) * OHW + gc0) * NF) + lane;

    #pragma unroll 4
    for (int j = 0; j < jmax; ++j) {
        float x02 = r0[j + 2];
        float x12 = r1[j + 2];
        float x22 = r2[j + 2];

        float acc = bia;
        acc = fmaf(x00, wf[0], acc);
        acc = fmaf(x01, wf[1], acc);
        acc = fmaf(x02, wf[2], acc);
        acc = fmaf(x10, wf[3], acc);
        acc = fmaf(x11, wf[4], acc);
        acc = fmaf(x12, wf[5], acc);
        acc = fmaf(x20, wf[6], acc);
        acc = fmaf(x21, wf[7], acc);
        acc = fmaf(x22, wf[8], acc);

        *optr = fmaxf(acc, 0.0f);
        optr += NF;

        x00 = x01; x01 = x02;
        x10 = x11; x11 = x12;
        x20 = x21; x21 = x22;
    }
}

extern "C" void kernel_launch(void* const* d_in, const int* in_sizes, int n_in,
                              void* d_out, int out_size)
{
    const float* x    = (const float*)d_in[0];   // (32,512,512)
    const float* kw   = (const float*)d_in[1];   // (32,3,3)
    const float* bias = (const float*)d_in[2];   // (32,)
    float* out = (float*)d_out;                  // (32,510,510,32)

    dim3 grid((OHW + TC - 1) / TC,   // 4
              (OHW + TR - 1) / TR,   // 64
              BATCH);                // 32
    cwtconv2d_kernel<<<grid, 256>>>(x, kw, bias, out);
}